// round 12
// baseline (speedup 1.0000x reference)
#include <cuda_runtime.h>
#include <cuda_bf16.h>

#define NM 3
#define NB 64
#define ND 512
#define NDH 128
#define INV_SCALE 0.04419417382415922f   // 1/sqrt(512)
#define INV_HIST_B 0.003125f             // 1/(64*5)
#define LOG2E 1.4426950408889634f
#define SPLITK 8
#define KB (ND / SPLITK)                 // 64 k per gemm block

typedef unsigned long long ull;

// ---------------- scratch (static device globals; no allocation) ----------------
__device__ __align__(16) float g_pp [SPLITK * NM * NB * ND];  // split-k partials
__device__ __align__(16) float g_W1t[NM * ND * NDH];          // imp_W1^T: [i][k][dh]
__device__ __align__(16) float g_W2t[NM * NDH * ND];          // imp_W2^T: [i][kh][d]
__device__ __align__(16) float g_wf [NM * NB * ND];
__device__ float g_rowsum[NM * NB];
__device__ __align__(16) float g_att1[NM * NB * ND];
__device__ __align__(16) float g_att2[NM * NB * ND];
__device__ int g_cnt[NM];   // stage-A fan-in; reset by pass consumers (init 0)
__device__ int g_cnt2;      // pass fan-in; reset by k_fused (init 0)

// ---------------- packed f32x2 helpers ----------------
__device__ __forceinline__ ull pk2(float lo, float hi) {
    ull r; asm("mov.b64 %0, {%1, %2};" : "=l"(r) : "f"(lo), "f"(hi)); return r;
}
__device__ __forceinline__ void upk2(ull v, float& lo, float& hi) {
    asm("mov.b64 {%0, %1}, %2;" : "=f"(lo), "=f"(hi) : "l"(v));
}
__device__ __forceinline__ ull mul2(ull a, ull b) {
    ull r; asm("mul.rn.f32x2 %0, %1, %2;" : "=l"(r) : "l"(a), "l"(b)); return r;
}
__device__ __forceinline__ ull add2(ull a, ull b) {
    ull r; asm("add.rn.f32x2 %0, %1, %2;" : "=l"(r) : "l"(a), "l"(b)); return r;
}
__device__ __forceinline__ ull fma2(ull a, ull b, ull c) {
    ull r; asm("fma.rn.f32x2 %0, %1, %2, %3;" : "=l"(r) : "l"(a), "l"(b), "l"(c)); return r;
}
__device__ __forceinline__ float ex2f(float x) {
    float r; asm("ex2.approx.ftz.f32 %0, %1;" : "=f"(r) : "f"(x)); return r;
}

// ---------------- reduction helpers ----------------
__device__ __forceinline__ float warpRedSum(float v) {
#pragma unroll
    for (int o = 16; o; o >>= 1) v += __shfl_xor_sync(0xffffffffu, v, o);
    return v;
}
// dual interleaved warp sum (independent chains overlap SHFL latency)
__device__ __forceinline__ void warpRedSum2(float& a, float& b) {
#pragma unroll
    for (int o = 16; o; o >>= 1) {
        a += __shfl_xor_sync(0xffffffffu, a, o);
        b += __shfl_xor_sync(0xffffffffu, b, o);
    }
}

// block reduce over 256 threads (8 warps)
__device__ __forceinline__ float blockRed256(float v, float* sred, float* sb,
                                             int lane, int wid) {
    float s = warpRedSum(v);
    if (lane == 0) sred[wid] = s;
    __syncthreads();
    if (wid == 0) {
        float t = (lane < 8) ? sred[lane] : 0.f;
        t = warpRedSum(t);
        if (lane == 0) *sb = t;
    }
    __syncthreads();
    return *sb;
}

// ---------------- K1: fused stage A (round-7 exact + g_cnt2 reset) ----------------
// blocks [0,192):   split-K proj GEMM (ks = b&7, nt = (b>>3)&7, i = b>>6)
// blocks [192,576): W1/W2 transposes (128 per mode)
// blocks [576,768): post (partial-sum + LN + imp1 + imp2 + wf), fan-in on g_cnt
#define KC 16
#define LDS_PAD 68
#define GEMM_BLOCKS (SPLITK * 8 * NM)            // 192
#define TRANS_BLOCKS (64 * 2 * NM)               // 384
#define PROD_PER_MODE (64 + 128)                 // gemm + transpose blocks per mode
#define PASS_BLOCKS (NM * ND)                    // 1536
#define FINAL_BLOCKS 128
__global__ __launch_bounds__(256) void k_fused(
        const float* __restrict__ x, const float* __restrict__ W,
        const float* __restrict__ W1, const float* __restrict__ W2,
        const float* __restrict__ pb, const float* __restrict__ lg,
        const float* __restrict__ lb, const float* __restrict__ b1,
        const float* __restrict__ b2) {
    int bid = blockIdx.x;
    int tid = threadIdx.x;
    if (bid == 0 && tid == 0) g_cnt2 = 0;   // reset pass fan-in for this replay
    if (bid < GEMM_BLOCKS) {
        // ---- proj GEMM ----
        int ks = bid & 7, nt = (bid >> 3) & 7, i = bid >> 6;
        int n0 = nt * 64;
        int tx = tid & 15, ty = tid >> 4;
        int kk = tid & 15, rr = tid >> 4;

        __shared__ float Xs[KC * LDS_PAD];
        __shared__ float Ws[KC * LDS_PAD];

        const float* xb = x + (size_t)i * NB * ND;
        const float* wb = W + (size_t)i * ND * ND + (size_t)n0 * ND;

        float c[4][4];
#pragma unroll
        for (int q = 0; q < 4; q++)
#pragma unroll
            for (int r = 0; r < 4; r++) c[q][r] = 0.f;

#pragma unroll
        for (int cc = 0; cc < KB / KC; cc++) {
            int k0 = ks * KB + cc * KC;
#pragma unroll
            for (int r = 0; r < 4; r++) {
                int b = rr + r * 16;
                Xs[kk * LDS_PAD + b] = xb[(size_t)b * ND + k0 + kk];
                Ws[kk * LDS_PAD + b] = wb[(size_t)b * ND + k0 + kk];
            }
            __syncthreads();
#pragma unroll
            for (int k2 = 0; k2 < KC; k2++) {
                float4 xa = *(const float4*)&Xs[k2 * LDS_PAD + ty * 4];
                float4 wa = *(const float4*)&Ws[k2 * LDS_PAD + tx * 4];
                float xv[4] = {xa.x, xa.y, xa.z, xa.w};
                float wv[4] = {wa.x, wa.y, wa.z, wa.w};
#pragma unroll
                for (int q = 0; q < 4; q++)
#pragma unroll
                    for (int r = 0; r < 4; r++) c[q][r] = fmaf(xv[q], wv[r], c[q][r]);
            }
            __syncthreads();
        }
#pragma unroll
        for (int q = 0; q < 4; q++) {
            int b = ty * 4 + q;
            float4 o = make_float4(c[q][0], c[q][1], c[q][2], c[q][3]);
            *(float4*)&g_pp[((size_t)(ks * NM * NB) + i * NB + b) * ND + n0 + tx * 4] = o;
        }
        __threadfence();
        __syncthreads();
        if (tid == 0) atomicAdd(&g_cnt[i], 1);
    } else if (bid < GEMM_BLOCKS + TRANS_BLOCKS) {
        // ---- transpose: z < NM -> W1 mode z; else W2 mode z-NM ----
        __shared__ float tile[32][33];
        int idx = bid - GEMM_BLOCKS;
        int t = idx & 63;
        int z = idx >> 6;
        int isW2 = (z >= NM);
        int i = isW2 ? z - NM : z;
        int R = isW2 ? ND : NDH;
        int C = isW2 ? NDH : ND;
        int c0 = (isW2 ? (t & 3) : (t & 15)) * 32;
        int r0 = (isW2 ? (t >> 2) : (t >> 4)) * 32;
        const float* s = (isW2 ? W2 : W1) + (size_t)i * R * C;
        float* dd = (isW2 ? g_W2t : g_W1t) + (size_t)i * R * C;
        int tx = tid & 31, ty = tid >> 5;
#pragma unroll
        for (int rr = ty; rr < 32; rr += 8)
            tile[rr][tx] = s[(size_t)(r0 + rr) * C + c0 + tx];
        __syncthreads();
#pragma unroll
        for (int cc = ty; cc < 32; cc += 8)
            dd[(size_t)(c0 + cc) * R + r0 + tx] = tile[tx][cc];
        __threadfence();
        __syncthreads();
        if (tid == 0) atomicAdd(&g_cnt[i], 1);
    } else {
        // ---- post: per-(i,b), 256 threads, 2 d per thread ----
        int idx = bid - GEMM_BLOCKS - TRANS_BLOCKS;
        int i = idx >> 6, b = idx & 63;
        int lane = tid & 31, wid = tid >> 5;
        int d0 = tid, d1 = tid + 256;

        __shared__ float proj_s[ND];
        __shared__ float sP[2 * NDH];
        __shared__ float h_s[NDH];
        __shared__ float sred[8];
        __shared__ float sb;

        // fan-in: wait for all producers of this mode
        if (tid == 0) {
            while (atomicAdd(&g_cnt[i], 0) < PROD_PER_MODE) __nanosleep(64);
        }
        __syncthreads();
        __threadfence();

        float acc0 = 0.f, acc1 = 0.f;
#pragma unroll
        for (int s = 0; s < SPLITK; s++) {
            const float* pp = g_pp + ((size_t)(s * NM * NB) + i * NB + b) * ND;
            acc0 += pp[d0];
            acc1 += pp[d1];
        }
        acc0 += pb[i * ND + d0];
        acc1 += pb[i * ND + d1];

        float mu = blockRed256(acc0 + acc1, sred, &sb, lane, wid) * (1.f / ND);
        float dv0 = acc0 - mu, dv1 = acc1 - mu;
        float var = blockRed256(dv0 * dv0 + dv1 * dv1, sred, &sb, lane, wid) * (1.f / ND);
        float rstd = rsqrtf(var + 1e-5f);
        float p0 = fmaxf(dv0 * rstd * lg[i * ND + d0] + lb[i * ND + d0], 0.f);
        float p1 = fmaxf(dv1 * rstd * lg[i * ND + d1] + lb[i * ND + d1], 0.f);
        proj_s[d0] = p0;
        proj_s[d1] = p1;
        __syncthreads();

        // imp1: 128 dh x 2 k-splits of 256, 4 accumulators each
        {
            int dh = tid & 127, k4 = tid >> 7;
            const float* Wt = g_W1t + (size_t)i * ND * NDH + (size_t)(k4 * 256) * NDH + dh;
            const float* ps = proj_s + k4 * 256;
            float a[4] = {0.f, 0.f, 0.f, 0.f};
#pragma unroll 8
            for (int k = 0; k < 256; k += 4) {
                a[0] = fmaf(Wt[(size_t)(k + 0) * NDH], ps[k + 0], a[0]);
                a[1] = fmaf(Wt[(size_t)(k + 1) * NDH], ps[k + 1], a[1]);
                a[2] = fmaf(Wt[(size_t)(k + 2) * NDH], ps[k + 2], a[2]);
                a[3] = fmaf(Wt[(size_t)(k + 3) * NDH], ps[k + 3], a[3]);
            }
            sP[k4 * NDH + dh] = (a[0] + a[1]) + (a[2] + a[3]);
        }
        __syncthreads();
        if (tid < NDH) {
            float hs = sP[tid] + sP[NDH + tid] + b1[i * NDH + tid];
            h_s[tid] = fmaxf(hs, 0.f);
        }
        __syncthreads();

        // imp2: both d's, 4 accumulators each
        {
            const float* W2t = g_W2t + (size_t)i * NDH * ND;
            float c0[4] = {0.f, 0.f, 0.f, 0.f};
            float c1[4] = {0.f, 0.f, 0.f, 0.f};
#pragma unroll 4
            for (int kh = 0; kh < NDH; kh += 4) {
#pragma unroll
                for (int j = 0; j < 4; j++) {
                    float h = h_s[kh + j];
                    c0[j] = fmaf(W2t[(size_t)(kh + j) * ND + d0], h, c0[j]);
                    c1[j] = fmaf(W2t[(size_t)(kh + j) * ND + d1], h, c1[j]);
                }
            }
            float a20 = (c0[0] + c0[1]) + (c0[2] + c0[3]) + b2[i * ND + d0];
            float a21 = (c1[0] + c1[1]) + (c1[2] + c1[3]) + b2[i * ND + d1];
            float cw0 = 1.f / (1.f + __expf(-a20));
            float cw1 = 1.f / (1.f + __expf(-a21));
            float wf0 = p0 * cw0, wf1 = p1 * cw1;
            float* wfo = g_wf + ((size_t)i * NB + b) * ND;
            wfo[d0] = wf0;
            wfo[d1] = wf1;
            float rs = blockRed256(wf0 + wf1, sred, &sb, lane, wid);
            if (tid == 0) g_rowsum[i * NB + b] = rs;
        }
    }
}

// ---------------- K2: pass1+pass2 (blocks [0,1536)) + final (blocks [1536,1664)) ----------------
__global__ __launch_bounds__(256, 3) void k_pass(const float* __restrict__ modal_bias,
                                                 const float* __restrict__ constraint,
                                                 const float* __restrict__ gamma,
                                                 float* __restrict__ out) {
    __shared__ ull sH[8][256];
    int tid = threadIdx.x, lane = tid & 31, wid = tid >> 5;

    if (blockIdx.x >= PASS_BLOCKS) {
        // ---- final consumer: fuse + attention weights + g_cnt reset ----
        if (tid == 0) {
            while (atomicAdd(&g_cnt2, 0) < PASS_BLOCKS) __nanosleep(64);
        }
        __syncthreads();
        __threadfence();
        int idx = (blockIdx.x - PASS_BLOCKS) * 256 + tid;   // [0, 32768)
        int b = idx >> 9, d = idx & 511;
        if (idx < NM) g_cnt[idx] = 0;   // reset stage-A fan-in for next replay
        float acc = 0.f;
#pragma unroll
        for (int i = 0; i < NM; i++) {
            int j1 = (i == 0) ? 1 : 0;
            int j2 = (i == 2) ? 1 : 2;
            float g1 = 1.f / (1.f + __expf(-gamma[i * NM + j1]));
            float g2 = 1.f / (1.f + __expf(-gamma[i * NM + j2]));
            int o = ((i << 6) + b) * ND + d;
            acc += g_wf[o] + 0.5f * (g1 * g_att1[o] + g2 * g_att2[o]);
        }
        out[b * ND + d] = acc * (1.0f / 3.0f);
        if (idx == 0) {
            float sc[NM];
            float mx = -3.4e38f;
#pragma unroll
            for (int i = 0; i < NM; i++) {
                int j1 = (i == 0) ? 1 : 0;
                int j2 = (i == 2) ? 1 : 2;
                float g1 = 1.f / (1.f + __expf(-gamma[i * NM + j1]));
                float g2 = 1.f / (1.f + __expf(-gamma[i * NM + j2]));
                sc[i] = 0.5f * (g1 + g2);
                mx = fmaxf(mx, sc[i]);
            }
            float s = 0.f;
#pragma unroll
            for (int i = 0; i < NM; i++) { sc[i] = __expf(sc[i] - mx); s += sc[i]; }
#pragma unroll
            for (int i = 0; i < NM; i++) out[NB * ND + i] = sc[i] / s;
        }
        return;
    }

    int i = blockIdx.x >> 9;          // [0, 1536)
    int d = blockIdx.x & 511;
    int j1 = (i == 0) ? 1 : 0;
    int j2 = (i == 2) ? 1 : 2;
    float c = constraint[i];
    float bias1 = modal_bias[i * NM + j1];
    float bias2 = modal_bias[i * NM + j2];
    float B = 0.8f * c * LOG2E;          // pass-A clamp half-width (pre-scaled by 0.8)
    float CL = c * LOG2E;                // clip bound in ex2 domain
    ull C02 = pk2(0.2f, 0.2f);
    ull C08 = pk2(0.8f, 0.8f);
    ull NB2 = pk2(-B, -B);
    ull PB2 = pk2(B, B);
    ull CL2 = pk2(CL, CL);
    ull NCL2 = pk2(-CL, -CL);
    ull IHB2 = pk2(INV_HIST_B, INV_HIST_B);

    const float* wfi = g_wf + (size_t)i * NB * ND;
    const float* wf1 = g_wf + (size_t)j1 * NB * ND;
    const float* wf2 = g_wf + (size_t)j2 * NB * ND;
    const float* rs1 = g_rowsum + j1 * NB;
    const float* rs2 = g_rowsum + j2 * NB;

    // a (pre-scaled into ex2 domain) for this warp's 8 batch rows: lanes 0..7
    float aL_r = 0.f;
    if (lane < 8) aL_r = wfi[(size_t)(wid * 8 + lane) * ND + d] * (INV_SCALE * LOG2E);

    ull H2[8];
#pragma unroll
    for (int kp = 0; kp < 8; kp++) H2[kp] = 0ull;

    // ---- pass A (hist = 0), pair (i, j1): f = 0.2*cur + clamp(0.8*cur, -B, B) ----
#pragma unroll
    for (int t = 0; t < 8; t++) {
        int b = wid * 8 + t;
        float a = __shfl_sync(0xffffffffu, aL_r, t);
        ull a2 = pk2(a, a);
        const ulonglong2* vr = (const ulonglong2*)(wf1 + (size_t)b * ND);
        ulonglong2 q0 = vr[lane], q1 = vr[32 + lane], q2 = vr[64 + lane], q3 = vr[96 + lane];
        ull vv[8] = {q0.x, q0.y, q1.x, q1.y, q2.x, q2.y, q3.x, q3.y};
        ull ps2 = 0ull, pd2 = 0ull;
#pragma unroll
        for (int kp = 0; kp < 8; kp++) {
            ull cur2 = mul2(a2, vv[kp]);
            ull u2 = fma2(cur2, C02, NB2);
            ull w2 = fma2(cur2, C02, PB2);
            float x0, x1, u0, u1, w0, w1;
            upk2(cur2, x0, x1); upk2(u2, u0, u1); upk2(w2, w0, w1);
            float f0 = fminf(fmaxf(x0, u0), w0);
            float f1 = fminf(fmaxf(x1, u1), w1);
            H2[kp] = add2(H2[kp], pk2(f0, f1));
            ull pp = pk2(ex2f(f0), ex2f(f1));
            ps2 = add2(ps2, pp);
            pd2 = fma2(pp, vv[kp], pd2);
        }
        float s0, s1, dd0, dd1;
        upk2(ps2, s0, s1); upk2(pd2, dd0, dd1);
        float ps = s0 + s1, pd = dd0 + dd1;
        warpRedSum2(ps, pd);
        if (lane == 0)
            g_att1[((size_t)i * NB + b) * ND + d] = pd / ps + bias1 * rs1[b];
    }

    // fan-in history partials across all 8 warps of this d
#pragma unroll
    for (int kp = 0; kp < 8; kp++) sH[wid][kp * 32 + lane] = H2[kp];
    __syncthreads();
    // pass-B bounds: f = 0.2*cur + clamp(0.8*cur, 0.8*(H-C), 0.8*(H+C))
    ull lo2[8], hi2[8];
#pragma unroll
    for (int kp = 0; kp < 8; kp++) {
        ull hsum = add2(add2(sH[0][kp * 32 + lane], sH[1][kp * 32 + lane]),
                        add2(sH[2][kp * 32 + lane], sH[3][kp * 32 + lane]));
        hsum = add2(hsum, add2(add2(sH[4][kp * 32 + lane], sH[5][kp * 32 + lane]),
                               add2(sH[6][kp * 32 + lane], sH[7][kp * 32 + lane])));
        ull hist2 = mul2(hsum, IHB2);
        lo2[kp] = mul2(add2(hist2, NCL2), C08);
        hi2[kp] = mul2(add2(hist2, CL2), C08);
    }

    // ---- pass B, pair (i, j2) ----
#pragma unroll
    for (int t = 0; t < 8; t++) {
        int b = wid * 8 + t;
        float a = __shfl_sync(0xffffffffu, aL_r, t);
        ull a2 = pk2(a, a);
        const ulonglong2* vr = (const ulonglong2*)(wf2 + (size_t)b * ND);
        ulonglong2 q0 = vr[lane], q1 = vr[32 + lane], q2 = vr[64 + lane], q3 = vr[96 + lane];
        ull vv[8] = {q0.x, q0.y, q1.x, q1.y, q2.x, q2.y, q3.x, q3.y};
        ull ps2 = 0ull, pd2 = 0ull;
#pragma unroll
        for (int kp = 0; kp < 8; kp++) {
            ull cur2 = mul2(a2, vv[kp]);
            ull s2 = mul2(cur2, C08);
            float s0, s1, l0, l1, hh0, hh1;
            upk2(s2, s0, s1);
            upk2(lo2[kp], l0, l1);
            upk2(hi2[kp], hh0, hh1);
            float cl0 = fminf(fmaxf(s0, l0), hh0);
            float cl1 = fminf(fmaxf(s1, l1), hh1);
            ull f2 = fma2(cur2, C02, pk2(cl0, cl1));
            float f0, f1;
            upk2(f2, f0, f1);
            ull pp = pk2(ex2f(f0), ex2f(f1));
            ps2 = add2(ps2, pp);
            pd2 = fma2(pp, vv[kp], pd2);
        }
        float s0, s1, dd0, dd1;
        upk2(ps2, s0, s1); upk2(pd2, dd0, dd1);
        float ps = s0 + s1, pd = dd0 + dd1;
        warpRedSum2(ps, pd);
        if (lane == 0)
            g_att2[((size_t)i * NB + b) * ND + d] = pd / ps + bias2 * rs2[b];
    }

    // signal pass completion (for the final consumer blocks)
    __threadfence();
    __syncthreads();
    if (tid == 0) atomicAdd(&g_cnt2, 1);
}

extern "C" void kernel_launch(void* const* d_in, const int* in_sizes, int n_in,
                              void* d_out, int out_size) {
    const float* x          = (const float*)d_in[0];
    const float* proj_W     = (const float*)d_in[1];
    const float* proj_b     = (const float*)d_in[2];
    const float* ln_g       = (const float*)d_in[3];
    const float* ln_b       = (const float*)d_in[4];
    const float* imp_W1     = (const float*)d_in[5];
    const float* imp_b1     = (const float*)d_in[6];
    const float* imp_W2     = (const float*)d_in[7];
    const float* imp_b2     = (const float*)d_in[8];
    const float* gamma      = (const float*)d_in[9];
    const float* modal_bias = (const float*)d_in[10];
    const float* constraint = (const float*)d_in[11];
    float* out = (float*)d_out;

    k_fused<<<GEMM_BLOCKS + TRANS_BLOCKS + NM * NB, 256>>>(
        x, proj_W, imp_W1, imp_W2, proj_b, ln_g, ln_b, imp_b1, imp_b2);
    k_pass<<<PASS_BLOCKS + FINAL_BLOCKS, 256>>>(modal_bias, constraint, gamma, out);
}

// round 13
// speedup vs baseline: 1.0575x; 1.0575x over previous
#include <cuda_runtime.h>
#include <cuda_bf16.h>

#define NM 3
#define NB 64
#define ND 512
#define NDH 128
#define INV_SCALE 0.04419417382415922f   // 1/sqrt(512)
#define INV_HIST_B 0.003125f             // 1/(64*5)
#define LOG2E 1.4426950408889634f
#define SPLITK 8
#define KB (ND / SPLITK)                 // 64 k per gemm block

typedef unsigned long long ull;

// ---------------- scratch (static device globals; no allocation) ----------------
__device__ __align__(16) float g_pp [SPLITK * NM * NB * ND];  // split-k partials
__device__ __align__(16) float g_W1t[NM * ND * NDH];          // imp_W1^T: [i][k][dh]
__device__ __align__(16) float g_W2t[NM * NDH * ND];          // imp_W2^T: [i][kh][d]
__device__ __align__(16) float g_wf [NM * NB * ND];
__device__ float g_rowsum[NM * NB];
__device__ __align__(16) float g_att1[NM * NB * ND];
__device__ __align__(16) float g_att2[NM * NB * ND];
__device__ int g_cnt[NM];   // fan-in counters; reset by k_final each run (init 0)

// ---------------- packed f32x2 helpers ----------------
__device__ __forceinline__ ull pk2(float lo, float hi) {
    ull r; asm("mov.b64 %0, {%1, %2};" : "=l"(r) : "f"(lo), "f"(hi)); return r;
}
__device__ __forceinline__ void upk2(ull v, float& lo, float& hi) {
    asm("mov.b64 {%0, %1}, %2;" : "=f"(lo), "=f"(hi) : "l"(v));
}
__device__ __forceinline__ ull mul2(ull a, ull b) {
    ull r; asm("mul.rn.f32x2 %0, %1, %2;" : "=l"(r) : "l"(a), "l"(b)); return r;
}
__device__ __forceinline__ ull add2(ull a, ull b) {
    ull r; asm("add.rn.f32x2 %0, %1, %2;" : "=l"(r) : "l"(a), "l"(b)); return r;
}
__device__ __forceinline__ ull fma2(ull a, ull b, ull c) {
    ull r; asm("fma.rn.f32x2 %0, %1, %2, %3;" : "=l"(r) : "l"(a), "l"(b), "l"(c)); return r;
}
__device__ __forceinline__ float ex2f(float x) {
    float r; asm("ex2.approx.ftz.f32 %0, %1;" : "=f"(r) : "f"(x)); return r;
}
// volatile shared ld of a 16B (lo,hi) pair — volatile so ptxas cannot hoist
// the loop-invariant load back into registers (that would defeat the reg diet)
__device__ __forceinline__ void lds_pair(ull& lo, ull& hi, const void* p) {
    unsigned a = (unsigned)__cvta_generic_to_shared(p);
    asm volatile("ld.shared.v2.u64 {%0, %1}, [%2];" : "=l"(lo), "=l"(hi) : "r"(a));
}

// ---------------- reduction helpers ----------------
__device__ __forceinline__ float warpRedSum(float v) {
#pragma unroll
    for (int o = 16; o; o >>= 1) v += __shfl_xor_sync(0xffffffffu, v, o);
    return v;
}
// dual interleaved warp sum (independent chains overlap SHFL latency)
__device__ __forceinline__ void warpRedSum2(float& a, float& b) {
#pragma unroll
    for (int o = 16; o; o >>= 1) {
        a += __shfl_xor_sync(0xffffffffu, a, o);
        b += __shfl_xor_sync(0xffffffffu, b, o);
    }
}

// block reduce over 256 threads (8 warps)
__device__ __forceinline__ float blockRed256(float v, float* sred, float* sb,
                                             int lane, int wid) {
    float s = warpRedSum(v);
    if (lane == 0) sred[wid] = s;
    __syncthreads();
    if (wid == 0) {
        float t = (lane < 8) ? sred[lane] : 0.f;
        t = warpRedSum(t);
        if (lane == 0) *sb = t;
    }
    __syncthreads();
    return *sb;
}

// ---------------- K1: fused stage A (round-7 exact) ----------------
// blocks [0,192):   split-K proj GEMM (ks = b&7, nt = (b>>3)&7, i = b>>6)
// blocks [192,576): W1/W2 transposes (128 per mode)
// blocks [576,768): post (partial-sum + LN + imp1 + imp2 + wf), fan-in on g_cnt
#define KC 16
#define LDS_PAD 68
#define GEMM_BLOCKS (SPLITK * 8 * NM)            // 192
#define TRANS_BLOCKS (64 * 2 * NM)               // 384
#define PROD_PER_MODE (64 + 128)                 // gemm + transpose blocks per mode
__global__ __launch_bounds__(256) void k_fused(
        const float* __restrict__ x, const float* __restrict__ W,
        const float* __restrict__ W1, const float* __restrict__ W2,
        const float* __restrict__ pb, const float* __restrict__ lg,
        const float* __restrict__ lb, const float* __restrict__ b1,
        const float* __restrict__ b2) {
    int bid = blockIdx.x;
    int tid = threadIdx.x;
    if (bid < GEMM_BLOCKS) {
        // ---- proj GEMM ----
        int ks = bid & 7, nt = (bid >> 3) & 7, i = bid >> 6;
        int n0 = nt * 64;
        int tx = tid & 15, ty = tid >> 4;
        int kk = tid & 15, rr = tid >> 4;

        __shared__ float Xs[KC * LDS_PAD];
        __shared__ float Ws[KC * LDS_PAD];

        const float* xb = x + (size_t)i * NB * ND;
        const float* wb = W + (size_t)i * ND * ND + (size_t)n0 * ND;

        float c[4][4];
#pragma unroll
        for (int q = 0; q < 4; q++)
#pragma unroll
            for (int r = 0; r < 4; r++) c[q][r] = 0.f;

#pragma unroll
        for (int cc = 0; cc < KB / KC; cc++) {
            int k0 = ks * KB + cc * KC;
#pragma unroll
            for (int r = 0; r < 4; r++) {
                int b = rr + r * 16;
                Xs[kk * LDS_PAD + b] = xb[(size_t)b * ND + k0 + kk];
                Ws[kk * LDS_PAD + b] = wb[(size_t)b * ND + k0 + kk];
            }
            __syncthreads();
#pragma unroll
            for (int k2 = 0; k2 < KC; k2++) {
                float4 xa = *(const float4*)&Xs[k2 * LDS_PAD + ty * 4];
                float4 wa = *(const float4*)&Ws[k2 * LDS_PAD + tx * 4];
                float xv[4] = {xa.x, xa.y, xa.z, xa.w};
                float wv[4] = {wa.x, wa.y, wa.z, wa.w};
#pragma unroll
                for (int q = 0; q < 4; q++)
#pragma unroll
                    for (int r = 0; r < 4; r++) c[q][r] = fmaf(xv[q], wv[r], c[q][r]);
            }
            __syncthreads();
        }
#pragma unroll
        for (int q = 0; q < 4; q++) {
            int b = ty * 4 + q;
            float4 o = make_float4(c[q][0], c[q][1], c[q][2], c[q][3]);
            *(float4*)&g_pp[((size_t)(ks * NM * NB) + i * NB + b) * ND + n0 + tx * 4] = o;
        }
        __threadfence();
        __syncthreads();
        if (tid == 0) atomicAdd(&g_cnt[i], 1);
    } else if (bid < GEMM_BLOCKS + TRANS_BLOCKS) {
        // ---- transpose: z < NM -> W1 mode z; else W2 mode z-NM ----
        __shared__ float tile[32][33];
        int idx = bid - GEMM_BLOCKS;
        int t = idx & 63;
        int z = idx >> 6;
        int isW2 = (z >= NM);
        int i = isW2 ? z - NM : z;
        int R = isW2 ? ND : NDH;
        int C = isW2 ? NDH : ND;
        int c0 = (isW2 ? (t & 3) : (t & 15)) * 32;
        int r0 = (isW2 ? (t >> 2) : (t >> 4)) * 32;
        const float* s = (isW2 ? W2 : W1) + (size_t)i * R * C;
        float* dd = (isW2 ? g_W2t : g_W1t) + (size_t)i * R * C;
        int tx = tid & 31, ty = tid >> 5;
#pragma unroll
        for (int rr = ty; rr < 32; rr += 8)
            tile[rr][tx] = s[(size_t)(r0 + rr) * C + c0 + tx];
        __syncthreads();
#pragma unroll
        for (int cc = ty; cc < 32; cc += 8)
            dd[(size_t)(c0 + cc) * R + r0 + tx] = tile[tx][cc];
        __threadfence();
        __syncthreads();
        if (tid == 0) atomicAdd(&g_cnt[i], 1);
    } else {
        // ---- post: per-(i,b), 256 threads, 2 d per thread ----
        int idx = bid - GEMM_BLOCKS - TRANS_BLOCKS;
        int i = idx >> 6, b = idx & 63;
        int lane = tid & 31, wid = tid >> 5;
        int d0 = tid, d1 = tid + 256;

        __shared__ float proj_s[ND];
        __shared__ float sP[2 * NDH];
        __shared__ float h_s[NDH];
        __shared__ float sred[8];
        __shared__ float sb;

        // fan-in: wait for all producers of this mode
        if (tid == 0) {
            while (atomicAdd(&g_cnt[i], 0) < PROD_PER_MODE) __nanosleep(64);
        }
        __syncthreads();
        __threadfence();

        float acc0 = 0.f, acc1 = 0.f;
#pragma unroll
        for (int s = 0; s < SPLITK; s++) {
            const float* pp = g_pp + ((size_t)(s * NM * NB) + i * NB + b) * ND;
            acc0 += pp[d0];
            acc1 += pp[d1];
        }
        acc0 += pb[i * ND + d0];
        acc1 += pb[i * ND + d1];

        float mu = blockRed256(acc0 + acc1, sred, &sb, lane, wid) * (1.f / ND);
        float dv0 = acc0 - mu, dv1 = acc1 - mu;
        float var = blockRed256(dv0 * dv0 + dv1 * dv1, sred, &sb, lane, wid) * (1.f / ND);
        float rstd = rsqrtf(var + 1e-5f);
        float p0 = fmaxf(dv0 * rstd * lg[i * ND + d0] + lb[i * ND + d0], 0.f);
        float p1 = fmaxf(dv1 * rstd * lg[i * ND + d1] + lb[i * ND + d1], 0.f);
        proj_s[d0] = p0;
        proj_s[d1] = p1;
        __syncthreads();

        // imp1: 128 dh x 2 k-splits of 256, 4 accumulators each
        {
            int dh = tid & 127, k4 = tid >> 7;
            const float* Wt = g_W1t + (size_t)i * ND * NDH + (size_t)(k4 * 256) * NDH + dh;
            const float* ps = proj_s + k4 * 256;
            float a[4] = {0.f, 0.f, 0.f, 0.f};
#pragma unroll 8
            for (int k = 0; k < 256; k += 4) {
                a[0] = fmaf(Wt[(size_t)(k + 0) * NDH], ps[k + 0], a[0]);
                a[1] = fmaf(Wt[(size_t)(k + 1) * NDH], ps[k + 1], a[1]);
                a[2] = fmaf(Wt[(size_t)(k + 2) * NDH], ps[k + 2], a[2]);
                a[3] = fmaf(Wt[(size_t)(k + 3) * NDH], ps[k + 3], a[3]);
            }
            sP[k4 * NDH + dh] = (a[0] + a[1]) + (a[2] + a[3]);
        }
        __syncthreads();
        if (tid < NDH) {
            float hs = sP[tid] + sP[NDH + tid] + b1[i * NDH + tid];
            h_s[tid] = fmaxf(hs, 0.f);
        }
        __syncthreads();

        // imp2: both d's, 4 accumulators each
        {
            const float* W2t = g_W2t + (size_t)i * NDH * ND;
            float c0[4] = {0.f, 0.f, 0.f, 0.f};
            float c1[4] = {0.f, 0.f, 0.f, 0.f};
#pragma unroll 4
            for (int kh = 0; kh < NDH; kh += 4) {
#pragma unroll
                for (int j = 0; j < 4; j++) {
                    float h = h_s[kh + j];
                    c0[j] = fmaf(W2t[(size_t)(kh + j) * ND + d0], h, c0[j]);
                    c1[j] = fmaf(W2t[(size_t)(kh + j) * ND + d1], h, c1[j]);
                }
            }
            float a20 = (c0[0] + c0[1]) + (c0[2] + c0[3]) + b2[i * ND + d0];
            float a21 = (c1[0] + c1[1]) + (c1[2] + c1[3]) + b2[i * ND + d1];
            float cw0 = 1.f / (1.f + __expf(-a20));
            float cw1 = 1.f / (1.f + __expf(-a21));
            float wf0 = p0 * cw0, wf1 = p1 * cw1;
            float* wfo = g_wf + ((size_t)i * NB + b) * ND;
            wfo[d0] = wf0;
            wfo[d1] = wf1;
            float rs = blockRed256(wf0 + wf1, sred, &sb, lane, wid);
            if (tid == 0) g_rowsum[i * NB + b] = rs;
        }
    }
}

// ---------------- K2: fused pass1+pass2, one block per (i,d), 8 warps x 8 b ----------------
// History bounds live in a 4KB smem table (identical across warps) instead of
// 32 registers; volatile LDS keeps them out of the register file -> 4 blocks/SM.
__global__ __launch_bounds__(256, 4) void k_pass(const float* __restrict__ modal_bias,
                                                 const float* __restrict__ constraint) {
    int i = blockIdx.x >> 9;          // blockIdx.x in [0, 1536)
    int d = blockIdx.x & 511;
    int tid = threadIdx.x, lane = tid & 31, wid = tid >> 5;
    int j1 = (i == 0) ? 1 : 0;
    int j2 = (i == 2) ? 1 : 2;
    float c = constraint[i];
    float bias1 = modal_bias[i * NM + j1];
    float bias2 = modal_bias[i * NM + j2];
    float B = 0.8f * c * LOG2E;          // pass-A clamp half-width (pre-scaled by 0.8)
    float CL = c * LOG2E;                // clip bound in ex2 domain
    ull C02 = pk2(0.2f, 0.2f);
    ull C08 = pk2(0.8f, 0.8f);
    ull NB2 = pk2(-B, -B);
    ull PB2 = pk2(B, B);
    ull CL2 = pk2(CL, CL);
    ull NCL2 = pk2(-CL, -CL);
    ull IHB2 = pk2(INV_HIST_B, INV_HIST_B);

    const float* wfi = g_wf + (size_t)i * NB * ND;
    const float* wf1 = g_wf + (size_t)j1 * NB * ND;
    const float* wf2 = g_wf + (size_t)j2 * NB * ND;
    const float* rs1 = g_rowsum + j1 * NB;
    const float* rs2 = g_rowsum + j2 * NB;

    __shared__ ull sH[8][256];
    __shared__ __align__(16) ull loHi[8][32][2];   // [kp][lane][{lo,hi}]

    // a (pre-scaled into ex2 domain) for this warp's 8 batch rows: lanes 0..7
    float aL_r = 0.f;
    if (lane < 8) aL_r = wfi[(size_t)(wid * 8 + lane) * ND + d] * (INV_SCALE * LOG2E);

    ull H2[8];
#pragma unroll
    for (int kp = 0; kp < 8; kp++) H2[kp] = 0ull;

    // ---- pass A (hist = 0), pair (i, j1): f = 0.2*cur + clamp(0.8*cur, -B, B) ----
#pragma unroll
    for (int t = 0; t < 8; t++) {
        int b = wid * 8 + t;
        float a = __shfl_sync(0xffffffffu, aL_r, t);
        ull a2 = pk2(a, a);
        const ulonglong2* vr = (const ulonglong2*)(wf1 + (size_t)b * ND);
        ulonglong2 q0 = vr[lane], q1 = vr[32 + lane], q2 = vr[64 + lane], q3 = vr[96 + lane];
        ull vv[8] = {q0.x, q0.y, q1.x, q1.y, q2.x, q2.y, q3.x, q3.y};
        ull ps2 = 0ull, pd2 = 0ull;
#pragma unroll
        for (int kp = 0; kp < 8; kp++) {
            ull cur2 = mul2(a2, vv[kp]);
            ull u2 = fma2(cur2, C02, NB2);
            ull w2 = fma2(cur2, C02, PB2);
            float x0, x1, u0, u1, w0, w1;
            upk2(cur2, x0, x1); upk2(u2, u0, u1); upk2(w2, w0, w1);
            float f0 = fminf(fmaxf(x0, u0), w0);
            float f1 = fminf(fmaxf(x1, u1), w1);
            H2[kp] = add2(H2[kp], pk2(f0, f1));
            ull pp = pk2(ex2f(f0), ex2f(f1));
            ps2 = add2(ps2, pp);
            pd2 = fma2(pp, vv[kp], pd2);
        }
        float s0, s1, dd0, dd1;
        upk2(ps2, s0, s1); upk2(pd2, dd0, dd1);
        float ps = s0 + s1, pd = dd0 + dd1;
        warpRedSum2(ps, pd);
        if (lane == 0)
            g_att1[((size_t)i * NB + b) * ND + d] = pd / ps + bias1 * rs1[b];
    }

    // fan-in history partials across all 8 warps; each warp then builds the
    // bounds table for its own kp row (bounds depend only on (kp, lane))
#pragma unroll
    for (int kp = 0; kp < 8; kp++) sH[wid][kp * 32 + lane] = H2[kp];
    __syncthreads();
    {
        int e = wid * 32 + lane;
        ull hsum = add2(add2(sH[0][e], sH[1][e]), add2(sH[2][e], sH[3][e]));
        hsum = add2(hsum, add2(add2(sH[4][e], sH[5][e]), add2(sH[6][e], sH[7][e])));
        ull hist2 = mul2(hsum, IHB2);
        loHi[wid][lane][0] = mul2(add2(hist2, NCL2), C08);
        loHi[wid][lane][1] = mul2(add2(hist2, CL2), C08);
    }
    __syncthreads();

    // ---- pass B, pair (i, j2): f = 0.2*cur + clamp(0.8*cur, lo, hi) ----
#pragma unroll
    for (int t = 0; t < 8; t++) {
        int b = wid * 8 + t;
        float a = __shfl_sync(0xffffffffu, aL_r, t);
        ull a2 = pk2(a, a);
        const ulonglong2* vr = (const ulonglong2*)(wf2 + (size_t)b * ND);
        ulonglong2 q0 = vr[lane], q1 = vr[32 + lane], q2 = vr[64 + lane], q3 = vr[96 + lane];
        ull vv[8] = {q0.x, q0.y, q1.x, q1.y, q2.x, q2.y, q3.x, q3.y};
        ull ps2 = 0ull, pd2 = 0ull;
#pragma unroll
        for (int kp = 0; kp < 8; kp++) {
            ull lov, hiv;
            lds_pair(lov, hiv, &loHi[kp][lane][0]);
            ull cur2 = mul2(a2, vv[kp]);
            ull s2 = mul2(cur2, C08);
            float s0, s1, l0, l1, hh0, hh1;
            upk2(s2, s0, s1);
            upk2(lov, l0, l1);
            upk2(hiv, hh0, hh1);
            float cl0 = fminf(fmaxf(s0, l0), hh0);
            float cl1 = fminf(fmaxf(s1, l1), hh1);
            ull f2 = fma2(cur2, C02, pk2(cl0, cl1));
            float f0, f1;
            upk2(f2, f0, f1);
            ull pp = pk2(ex2f(f0), ex2f(f1));
            ps2 = add2(ps2, pp);
            pd2 = fma2(pp, vv[kp], pd2);
        }
        float s0, s1, dd0, dd1;
        upk2(ps2, s0, s1); upk2(pd2, dd0, dd1);
        float ps = s0 + s1, pd = dd0 + dd1;
        warpRedSum2(ps, pd);
        if (lane == 0)
            g_att2[((size_t)i * NB + b) * ND + d] = pd / ps + bias2 * rs2[b];
    }
}

// ---------------- K3: fuse + attention weights + counter reset ----------------
__global__ __launch_bounds__(128) void k_final(const float* __restrict__ gamma,
                                               float* __restrict__ out) {
    int idx = blockIdx.x * 128 + threadIdx.x;   // [0, 32768)
    int b = idx >> 9, d = idx & 511;
    if (idx < NM) g_cnt[idx] = 0;               // reset fan-in for next replay
    float acc = 0.f;
#pragma unroll
    for (int i = 0; i < NM; i++) {
        int j1 = (i == 0) ? 1 : 0;
        int j2 = (i == 2) ? 1 : 2;
        float g1 = 1.f / (1.f + __expf(-gamma[i * NM + j1]));
        float g2 = 1.f / (1.f + __expf(-gamma[i * NM + j2]));
        int o = ((i << 6) + b) * ND + d;
        acc += g_wf[o] + 0.5f * (g1 * g_att1[o] + g2 * g_att2[o]);
    }
    out[b * ND + d] = acc * (1.0f / 3.0f);
    if (idx == 0) {
        float sc[NM];
        float mx = -3.4e38f;
#pragma unroll
        for (int i = 0; i < NM; i++) {
            int j1 = (i == 0) ? 1 : 0;
            int j2 = (i == 2) ? 1 : 2;
            float g1 = 1.f / (1.f + __expf(-gamma[i * NM + j1]));
            float g2 = 1.f / (1.f + __expf(-gamma[i * NM + j2]));
            sc[i] = 0.5f * (g1 + g2);
            mx = fmaxf(mx, sc[i]);
        }
        float s = 0.f;
#pragma unroll
        for (int i = 0; i < NM; i++) { sc[i] = __expf(sc[i] - mx); s += sc[i]; }
#pragma unroll
        for (int i = 0; i < NM; i++) out[NB * ND + i] = sc[i] / s;
    }
}

extern "C" void kernel_launch(void* const* d_in, const int* in_sizes, int n_in,
                              void* d_out, int out_size) {
    const float* x          = (const float*)d_in[0];
    const float* proj_W     = (const float*)d_in[1];
    const float* proj_b     = (const float*)d_in[2];
    const float* ln_g       = (const float*)d_in[3];
    const float* ln_b       = (const float*)d_in[4];
    const float* imp_W1     = (const float*)d_in[5];
    const float* imp_b1     = (const float*)d_in[6];
    const float* imp_W2     = (const float*)d_in[7];
    const float* imp_b2     = (const float*)d_in[8];
    const float* gamma      = (const float*)d_in[9];
    const float* modal_bias = (const float*)d_in[10];
    const float* constraint = (const float*)d_in[11];
    float* out = (float*)d_out;

    k_fused<<<GEMM_BLOCKS + TRANS_BLOCKS + NM * NB, 256>>>(
        x, proj_W, imp_W1, imp_W2, proj_b, ln_g, ln_b, imp_b1, imp_b2);
    k_pass<<<NM * ND, 256>>>(modal_bias, constraint);
    k_final<<<NB * ND / 128, 128>>>(gamma, out);
}